// round 4
// baseline (speedup 1.0000x reference)
#include <cuda_runtime.h>
#include <cuda_fp16.h>
#include <cstdint>
#include <cstddef>

#define N_TOKENS 8192
#define NGROUP   32

// Scratch (device globals — no runtime allocation). Both fp16, stored as u32 pairs.
// g_xm2 : x_mixed  [g][t][i/2]   (64 MB)
// g_yp2 : y_parts  [t][g][o/2]   (64 MB)
__device__ uint32_t g_xm2[(size_t)NGROUP * N_TOKENS * 64];
__device__ uint32_t g_yp2[(size_t)N_TOKENS * NGROUP * 64];

// ---------------------------------------------------------------------------
__device__ __forceinline__ uint32_t smem_u32(const void* p) {
    uint32_t a;
    asm("{ .reg .u64 t; cvta.to.shared.u64 t, %1; cvt.u32.u64 %0, t; }"
        : "=r"(a) : "l"(p));
    return a;
}

__device__ __forceinline__ void ldsm_x4(uint32_t& r0, uint32_t& r1,
                                        uint32_t& r2, uint32_t& r3, uint32_t addr) {
    asm volatile("ldmatrix.sync.aligned.m8n8.x4.shared.b16 {%0,%1,%2,%3}, [%4];"
                 : "=r"(r0), "=r"(r1), "=r"(r2), "=r"(r3) : "r"(addr));
}

__device__ __forceinline__ void mma16816(float* c, const uint32_t* a,
                                         uint32_t b0, uint32_t b1) {
    asm volatile("mma.sync.aligned.m16n8k16.row.col.f32.f16.f16.f32 "
                 "{%0,%1,%2,%3}, {%4,%5,%6,%7}, {%8,%9}, {%0,%1,%2,%3};"
                 : "+f"(c[0]), "+f"(c[1]), "+f"(c[2]), "+f"(c[3])
                 : "r"(a[0]), "r"(a[1]), "r"(a[2]), "r"(a[3]), "r"(b0), "r"(b1));
}

// ---------------------------------------------------------------------------
// K1: stage-1 Hadamard. CTA = 2 tokens x 64 i-pairs. In-register 32-pt WHT
// over groups (unnormalized; 1/32 folded into K3), emit fp16 pairs.
// ---------------------------------------------------------------------------
__global__ void __launch_bounds__(128) k1_mix(const float* __restrict__ x) {
    const int tl = threadIdx.x >> 6;
    const int ip = threadIdx.x & 63;
    const int t  = blockIdx.x * 2 + tl;
    const float2* xr = (const float2*)(x + (size_t)t * 4096) + ip;

    float2 v[32];
#pragma unroll
    for (int e = 0; e < 32; e++) v[e] = __ldg(xr + e * 64);

#pragma unroll
    for (int s = 1; s < 32; s <<= 1) {
#pragma unroll
        for (int e = 0; e < 32; e++) {
            if ((e & s) == 0) {
                float2 a = v[e], b = v[e | s];
                v[e].x = a.x + b.x; v[e].y = a.y + b.y;
                v[e | s].x = a.x - b.x; v[e | s].y = a.y - b.y;
            }
        }
    }

#pragma unroll
    for (int g = 0; g < 32; g++) {
        __half2 h = __floats2half2_rn(v[g].x, v[g].y);
        g_xm2[((size_t)g * N_TOKENS + t) * 64 + ip] = *(uint32_t*)&h;
    }
}

// ---------------------------------------------------------------------------
// K2: per (token-tile tt, group g): C[128t x 128o] = A[128x128] * B[128x128]^T
// fp16 in, fp32 accumulate via mma.sync.m16n8k16. 256 threads = 8 warps,
// warp tile 32(m) x 64(n). SMEM tiles padded to 272 B/row (conflict-free
// ldmatrix). B built on the fly from packed ternary weights.
// NOTE: weight_packed arrives as int32 elements (harness materializes uint8
// as int32); each element holds one packed byte (4 x 2-bit ternary).
// ---------------------------------------------------------------------------
#define SMS 272                       // smem row stride (bytes): 256 data + 16 pad
#define TILE_BYTES (128 * SMS)        // 34816
#define K2_SMEM (2 * TILE_BYTES)      // 69632

__global__ void __launch_bounds__(256) k2_gemm(const int* __restrict__ wpk) {
    extern __shared__ char smem[];
    char* pA = smem;
    char* pB = smem + TILE_BYTES;
    const uint32_t sA = smem_u32(pA);
    const uint32_t sB = sA + TILE_BYTES;

    const int tid  = threadIdx.x;
    const int wid  = tid >> 5;
    const int lane = tid & 31;
    const int tt = blockIdx.x;
    const int g  = blockIdx.y;

    // ---- A fill: 128 rows x 256 B (128 fp16) from g_xm2 ----
    {
        const uint4* src = (const uint4*)(g_xm2 + ((size_t)g * N_TOKENS + (size_t)tt * 128) * 64);
#pragma unroll
        for (int it = 0; it < 8; it++) {
            int idx = tid + it * 256;             // 0..2047
            int r = idx >> 4, q = idx & 15;
            uint4 w = __ldg(src + (size_t)r * 16 + q);
            *(uint4*)(pA + r * SMS + q * 16) = w;
        }
    }

    // ---- B fill: unpack ternary -> fp16 {-1,0,1}. thread = (o, half-row) ----
    {
        const int o = tid >> 1, half = tid & 1;
        const int* row32 = wpk + ((size_t)g * 128 + o) * 32 + half * 16;
        char* brow = pB + o * SMS + half * 128;
#pragma unroll
        for (int c = 0; c < 16; c++) {
            uint32_t by = (uint32_t)__ldg(row32 + c) & 0xFFu;   // one packed byte
            uint32_t bits[4];
#pragma unroll
            for (int j = 0; j < 4; j++) {
                uint32_t v2 = (by >> (6 - 2 * j)) & 3u;
                bits[j] = (v2 == 1u) ? 0u : ((v2 == 2u) ? 0x3C00u : 0xBC00u);
            }
            uint2 pk = make_uint2(bits[0] | (bits[1] << 16), bits[2] | (bits[3] << 16));
            *(uint2*)(brow + c * 8) = pk;
        }
    }
    __syncthreads();

    // ---- main loop ----
    const int wm = (wid & 3) * 32;                // warp m-base (rows)
    const int wn = (wid >> 2) * 64;               // warp n-base (cols)

    const int a_row = (lane & 7) + ((lane >> 3) & 1) * 8;
    const int a_col = ((lane >> 4) & 1) * 16;
    const uint32_t aLane = sA + (wm + a_row) * SMS + a_col;

    const int b_row = (lane & 7) + ((lane >> 4) & 1) * 8;
    const int b_col = ((lane >> 3) & 1) * 16;
    const uint32_t bLane = sB + (wn + b_row) * SMS + b_col;

    float acc[2][8][4];
#pragma unroll
    for (int mt = 0; mt < 2; mt++)
#pragma unroll
        for (int nt = 0; nt < 8; nt++)
#pragma unroll
            for (int q = 0; q < 4; q++) acc[mt][nt][q] = 0.0f;

#pragma unroll
    for (int ks = 0; ks < 8; ks++) {
        uint32_t a[2][4];
#pragma unroll
        for (int mt = 0; mt < 2; mt++)
            ldsm_x4(a[mt][0], a[mt][1], a[mt][2], a[mt][3],
                    aLane + mt * 16 * SMS + ks * 32);
        uint32_t b[4][4];
#pragma unroll
        for (int n2 = 0; n2 < 4; n2++)
            ldsm_x4(b[n2][0], b[n2][1], b[n2][2], b[n2][3],
                    bLane + n2 * 16 * SMS + ks * 32);
#pragma unroll
        for (int mt = 0; mt < 2; mt++)
#pragma unroll
            for (int nt = 0; nt < 8; nt++) {
                uint32_t b0 = b[nt >> 1][(nt & 1) * 2 + 0];
                uint32_t b1 = b[nt >> 1][(nt & 1) * 2 + 1];
                mma16816(acc[mt][nt], a[mt], b0, b1);
            }
    }

    // ---- epilogue: fp16x2 stores to g_yp2 [t][g][o/2] ----
    const int m0 = tt * 128 + wm + (lane >> 2);
    const int n0 = wn + 2 * (lane & 3);
#pragma unroll
    for (int mt = 0; mt < 2; mt++) {
#pragma unroll
        for (int nt = 0; nt < 8; nt++) {
            int n = n0 + nt * 8;
            __half2 lo = __floats2half2_rn(acc[mt][nt][0], acc[mt][nt][1]);
            __half2 hi = __floats2half2_rn(acc[mt][nt][2], acc[mt][nt][3]);
            size_t r0 = ((size_t)(m0 + mt * 16) * 32 + g) * 64 + (n >> 1);
            size_t r1 = ((size_t)(m0 + mt * 16 + 8) * 32 + g) * 64 + (n >> 1);
            g_yp2[r0] = *(uint32_t*)&lo;
            g_yp2[r1] = *(uint32_t*)&hi;
        }
    }
}

// ---------------------------------------------------------------------------
// K3: stage-3 Hadamard over g + beta/32 scale, fp32 output.
// CTA = 2 tokens x 64 o-pairs.
// ---------------------------------------------------------------------------
__global__ void __launch_bounds__(128) k3_mix(const float* __restrict__ beta,
                                              float* __restrict__ y) {
    const int tl = threadIdx.x >> 6;
    const int oq = threadIdx.x & 63;
    const int t  = blockIdx.x * 2 + tl;
    const uint32_t* yr = g_yp2 + (size_t)t * 32 * 64 + oq;

    float2 v[32];
#pragma unroll
    for (int e = 0; e < 32; e++) {
        uint32_t pk = __ldg(yr + e * 64);
        __half2 h = *(__half2*)&pk;
        v[e] = __half22float2(h);
    }

#pragma unroll
    for (int s = 1; s < 32; s <<= 1) {
#pragma unroll
        for (int e = 0; e < 32; e++) {
            if ((e & s) == 0) {
                float2 a = v[e], b = v[e | s];
                v[e].x = a.x + b.x; v[e].y = a.y + b.y;
                v[e | s].x = a.x - b.x; v[e | s].y = a.y - b.y;
            }
        }
    }

    const float s0 = __ldg(beta + 2 * oq)     * (1.0f / 32.0f);
    const float s1 = __ldg(beta + 2 * oq + 1) * (1.0f / 32.0f);
    float2* out = (float2*)(y + (size_t)t * 4096) + oq;
#pragma unroll
    for (int h = 0; h < 32; h++) {
        float2 o;
        o.x = v[h].x * s0;
        o.y = v[h].y * s1;
        out[h * 64] = o;
    }
}

// ---------------------------------------------------------------------------
// Launch: inputs dispatched BY ELEMENT COUNT (order-proof).
//   x: 33554432 f32 | weight_packed: 131072 elements (int32, one byte each)
//   beta: 128 f32 | H: 1024 f32 (unused; Sylvester structure hardcoded)
// ---------------------------------------------------------------------------
extern "C" void kernel_launch(void* const* d_in, const int* in_sizes, int n_in,
                              void* d_out, int out_size) {
    const float* x    = nullptr;
    const int*   wp   = nullptr;
    const float* beta = nullptr;

    for (int i = 0; i < n_in; i++) {
        switch (in_sizes[i]) {
            case 33554432: x    = (const float*)d_in[i]; break;
            case 131072:   wp   = (const int*)d_in[i];   break;
            case 128:      beta = (const float*)d_in[i]; break;
            default: break;   // H (1024) ignored
        }
    }
    if (!x)    x    = (const float*)d_in[0];
    if (!wp)   wp   = (const int*)d_in[1];
    if (!beta) beta = (const float*)d_in[2];

    float* y = (float*)d_out;

    cudaFuncSetAttribute(k2_gemm, cudaFuncAttributeMaxDynamicSharedMemorySize, K2_SMEM);

    k1_mix<<<N_TOKENS / 2, 128>>>(x);
    k2_gemm<<<dim3(N_TOKENS / 128, NGROUP), 256, K2_SMEM>>>(wp);
    k3_mix<<<N_TOKENS / 2, 128>>>(beta, y);
}

// round 5
// speedup vs baseline: 1.2178x; 1.2178x over previous
#include <cuda_runtime.h>
#include <cuda_fp16.h>
#include <cstdint>
#include <cstddef>

#define N_TOKENS 8192
#define NGROUP   32

// Scratch (device globals — no runtime allocation).
// g_xm2 : x_mixed fp16 pairs [g][t][i/2]   (64 MB)
// g_yp2 : y_parts fp16 pairs [t][g][o/2]   (64 MB)
// g_wf16: decoded ternary weights fp16 [g][o][k], k contiguous (1 MB, L2-resident)
__device__ uint32_t g_xm2[(size_t)NGROUP * N_TOKENS * 64];
__device__ uint32_t g_yp2[(size_t)N_TOKENS * NGROUP * 64];
__device__ uint32_t g_wf16[(size_t)NGROUP * 128 * 64];

// ---------------------------------------------------------------------------
__device__ __forceinline__ uint32_t smem_u32(const void* p) {
    uint32_t a;
    asm("{ .reg .u64 t; cvta.to.shared.u64 t, %1; cvt.u32.u64 %0, t; }"
        : "=r"(a) : "l"(p));
    return a;
}

__device__ __forceinline__ void cp16(uint32_t s, const void* g) {
    asm volatile("cp.async.cg.shared.global [%0], [%1], 16;" :: "r"(s), "l"(g));
}
__device__ __forceinline__ void cp_commit_wait() {
    asm volatile("cp.async.commit_group;");
    asm volatile("cp.async.wait_group 0;");
}

__device__ __forceinline__ void ldsm_x4(uint32_t& r0, uint32_t& r1,
                                        uint32_t& r2, uint32_t& r3, uint32_t addr) {
    asm volatile("ldmatrix.sync.aligned.m8n8.x4.shared.b16 {%0,%1,%2,%3}, [%4];"
                 : "=r"(r0), "=r"(r1), "=r"(r2), "=r"(r3) : "r"(addr));
}

__device__ __forceinline__ void mma16816(float* c, const uint32_t* a,
                                         uint32_t b0, uint32_t b1) {
    asm volatile("mma.sync.aligned.m16n8k16.row.col.f32.f16.f16.f32 "
                 "{%0,%1,%2,%3}, {%4,%5,%6,%7}, {%8,%9}, {%0,%1,%2,%3};"
                 : "+f"(c[0]), "+f"(c[1]), "+f"(c[2]), "+f"(c[3])
                 : "r"(a[0]), "r"(a[1]), "r"(a[2]), "r"(a[3]), "r"(b0), "r"(b1));
}

// ---------------------------------------------------------------------------
// K0: decode packed ternary weights (int32, one byte per element) -> fp16
// matrix g_wf16[g][o][k]. Runs once per call, ~1 MB write.
// ---------------------------------------------------------------------------
__global__ void __launch_bounds__(256) k0_decode(const int* __restrict__ wpk) {
    const int g    = blockIdx.x;
    const int o    = threadIdx.x >> 1;
    const int half = threadIdx.x & 1;
    const int* row32 = wpk + ((size_t)g * 128 + o) * 32 + half * 16;
    uint2* dst = (uint2*)(g_wf16 + ((size_t)(g * 128 + o)) * 64 + half * 32);
#pragma unroll
    for (int c = 0; c < 16; c++) {
        uint32_t by = (uint32_t)__ldg(row32 + c) & 0xFFu;
        uint32_t bits[4];
#pragma unroll
        for (int j = 0; j < 4; j++) {
            uint32_t v2 = (by >> (6 - 2 * j)) & 3u;
            bits[j] = (v2 == 1u) ? 0u : ((v2 == 2u) ? 0x3C00u : 0xBC00u);
        }
        dst[c] = make_uint2(bits[0] | (bits[1] << 16), bits[2] | (bits[3] << 16));
    }
}

// ---------------------------------------------------------------------------
// K1: stage-1 Hadamard. CTA = 2 tokens x 64 i-pairs. In-register 32-pt WHT
// over groups (unnormalized; 1/32 folded into K3), emit fp16 pairs.
// ---------------------------------------------------------------------------
__global__ void __launch_bounds__(128) k1_mix(const float* __restrict__ x) {
    const int tl = threadIdx.x >> 6;
    const int ip = threadIdx.x & 63;
    const int t  = blockIdx.x * 2 + tl;
    const float2* xr = (const float2*)(x + (size_t)t * 4096) + ip;

    float2 v[32];
#pragma unroll
    for (int e = 0; e < 32; e++) v[e] = __ldcs(xr + e * 64);   // streaming read

#pragma unroll
    for (int s = 1; s < 32; s <<= 1) {
#pragma unroll
        for (int e = 0; e < 32; e++) {
            if ((e & s) == 0) {
                float2 a = v[e], b = v[e | s];
                v[e].x = a.x + b.x; v[e].y = a.y + b.y;
                v[e | s].x = a.x - b.x; v[e | s].y = a.y - b.y;
            }
        }
    }

#pragma unroll
    for (int g = 0; g < 32; g++) {
        __half2 h = __floats2half2_rn(v[g].x, v[g].y);
        g_xm2[((size_t)g * N_TOKENS + t) * 64 + ip] = *(uint32_t*)&h;
    }
}

// ---------------------------------------------------------------------------
// K2: per (token-tile tt, group g): C[128t x 128o] = A[128x128] * B[128x128]^T
// fp16 in, fp32 accumulate via mma.sync.m16n8k16. 256 threads = 8 warps,
// warp tile 32(m) x 64(n). SMEM tiles padded to 272 B/row. A and B filled
// via cp.async; B comes pre-decoded from g_wf16 (L2-resident).
// ---------------------------------------------------------------------------
#define SMS 272                       // smem row stride (bytes): 256 data + 16 pad
#define TILE_BYTES (128 * SMS)        // 34816
#define K2_SMEM (2 * TILE_BYTES)      // 69632

__global__ void __launch_bounds__(256) k2_gemm() {
    extern __shared__ char smem[];
    char* pA = smem;
    const uint32_t sA = smem_u32(pA);
    const uint32_t sB = sA + TILE_BYTES;

    const int tid  = threadIdx.x;
    const int wid  = tid >> 5;
    const int lane = tid & 31;
    const int tt = blockIdx.x;
    const int g  = blockIdx.y;

    // ---- A fill: 128 rows x 256 B from g_xm2 (cp.async, streaming) ----
    {
        const char* src = (const char*)(g_xm2 + ((size_t)g * N_TOKENS + (size_t)tt * 128) * 64);
#pragma unroll
        for (int it = 0; it < 8; it++) {
            int idx = tid + it * 256;             // 0..2047 -> (row, 16B chunk)
            int r = idx >> 4, q = idx & 15;
            cp16(sA + r * SMS + q * 16, src + (size_t)r * 256 + q * 16);
        }
    }
    // ---- B fill: 128 rows x 256 B from pre-decoded g_wf16 (L2 hit) ----
    {
        const char* srcB = (const char*)(g_wf16 + (size_t)g * 128 * 64);
        const int o = tid >> 1, half = tid & 1;
#pragma unroll
        for (int it = 0; it < 8; it++) {
            cp16(sB + o * SMS + half * 128 + it * 16,
                 srcB + (size_t)o * 256 + half * 128 + it * 16);
        }
    }
    cp_commit_wait();
    __syncthreads();

    // ---- main loop ----
    const int wm = (wid & 3) * 32;                // warp m-base (rows)
    const int wn = (wid >> 2) * 64;               // warp n-base (cols)

    const int a_row = (lane & 7) + ((lane >> 3) & 1) * 8;
    const int a_col = ((lane >> 4) & 1) * 16;
    const uint32_t aLane = sA + (wm + a_row) * SMS + a_col;

    const int b_row = (lane & 7) + ((lane >> 4) & 1) * 8;
    const int b_col = ((lane >> 3) & 1) * 16;
    const uint32_t bLane = sB + (wn + b_row) * SMS + b_col;

    float acc[2][8][4];
#pragma unroll
    for (int mt = 0; mt < 2; mt++)
#pragma unroll
        for (int nt = 0; nt < 8; nt++)
#pragma unroll
            for (int q = 0; q < 4; q++) acc[mt][nt][q] = 0.0f;

#pragma unroll
    for (int ks = 0; ks < 8; ks++) {
        uint32_t a[2][4];
#pragma unroll
        for (int mt = 0; mt < 2; mt++)
            ldsm_x4(a[mt][0], a[mt][1], a[mt][2], a[mt][3],
                    aLane + mt * 16 * SMS + ks * 32);
        uint32_t b[4][4];
#pragma unroll
        for (int n2 = 0; n2 < 4; n2++)
            ldsm_x4(b[n2][0], b[n2][1], b[n2][2], b[n2][3],
                    bLane + n2 * 16 * SMS + ks * 32);
#pragma unroll
        for (int mt = 0; mt < 2; mt++)
#pragma unroll
            for (int nt = 0; nt < 8; nt++) {
                uint32_t b0 = b[nt >> 1][(nt & 1) * 2 + 0];
                uint32_t b1 = b[nt >> 1][(nt & 1) * 2 + 1];
                mma16816(acc[mt][nt], a[mt], b0, b1);
            }
    }

    // ---- epilogue: fp16x2 stores to g_yp2 [t][g][o/2] ----
    const int m0 = tt * 128 + wm + (lane >> 2);
    const int n0 = wn + 2 * (lane & 3);
#pragma unroll
    for (int mt = 0; mt < 2; mt++) {
#pragma unroll
        for (int nt = 0; nt < 8; nt++) {
            int n = n0 + nt * 8;
            __half2 lo = __floats2half2_rn(acc[mt][nt][0], acc[mt][nt][1]);
            __half2 hi = __floats2half2_rn(acc[mt][nt][2], acc[mt][nt][3]);
            size_t r0 = ((size_t)(m0 + mt * 16) * 32 + g) * 64 + (n >> 1);
            size_t r1 = ((size_t)(m0 + mt * 16 + 8) * 32 + g) * 64 + (n >> 1);
            g_yp2[r0] = *(uint32_t*)&lo;
            g_yp2[r1] = *(uint32_t*)&hi;
        }
    }
}

// ---------------------------------------------------------------------------
// K3: stage-3 Hadamard over g + beta/32 scale, fp32 output.
// CTA = 2 tokens x 64 o-pairs.
// ---------------------------------------------------------------------------
__global__ void __launch_bounds__(128) k3_mix(const float* __restrict__ beta,
                                              float* __restrict__ y) {
    const int tl = threadIdx.x >> 6;
    const int oq = threadIdx.x & 63;
    const int t  = blockIdx.x * 2 + tl;
    const uint32_t* yr = g_yp2 + (size_t)t * 32 * 64 + oq;

    float2 v[32];
#pragma unroll
    for (int e = 0; e < 32; e++) {
        uint32_t pk = __ldcs(yr + e * 64);        // streaming read
        __half2 h = *(__half2*)&pk;
        v[e] = __half22float2(h);
    }

#pragma unroll
    for (int s = 1; s < 32; s <<= 1) {
#pragma unroll
        for (int e = 0; e < 32; e++) {
            if ((e & s) == 0) {
                float2 a = v[e], b = v[e | s];
                v[e].x = a.x + b.x; v[e].y = a.y + b.y;
                v[e | s].x = a.x - b.x; v[e | s].y = a.y - b.y;
            }
        }
    }

    const float s0 = __ldg(beta + 2 * oq)     * (1.0f / 32.0f);
    const float s1 = __ldg(beta + 2 * oq + 1) * (1.0f / 32.0f);
    float2* out = (float2*)(y + (size_t)t * 4096) + oq;
#pragma unroll
    for (int h = 0; h < 32; h++) {
        float2 o;
        o.x = v[h].x * s0;
        o.y = v[h].y * s1;
        __stcs(out + h * 64, o);                  // streaming write (never re-read)
    }
}

// ---------------------------------------------------------------------------
// Launch: inputs dispatched BY ELEMENT COUNT (order-proof).
//   x: 33554432 f32 | weight_packed: 131072 elements (int32, one byte each)
//   beta: 128 f32 | H: 1024 f32 (unused; Sylvester structure hardcoded)
// ---------------------------------------------------------------------------
extern "C" void kernel_launch(void* const* d_in, const int* in_sizes, int n_in,
                              void* d_out, int out_size) {
    const float* x    = nullptr;
    const int*   wp   = nullptr;
    const float* beta = nullptr;

    for (int i = 0; i < n_in; i++) {
        switch (in_sizes[i]) {
            case 33554432: x    = (const float*)d_in[i]; break;
            case 131072:   wp   = (const int*)d_in[i];   break;
            case 128:      beta = (const float*)d_in[i]; break;
            default: break;   // H (1024) ignored
        }
    }
    if (!x)    x    = (const float*)d_in[0];
    if (!wp)   wp   = (const int*)d_in[1];
    if (!beta) beta = (const float*)d_in[2];

    float* y = (float*)d_out;

    cudaFuncSetAttribute(k2_gemm, cudaFuncAttributeMaxDynamicSharedMemorySize, K2_SMEM);

    k0_decode<<<NGROUP, 256>>>(wp);
    k1_mix<<<N_TOKENS / 2, 128>>>(x);
    k2_gemm<<<dim3(N_TOKENS / 128, NGROUP), 256, K2_SMEM>>>();
    k3_mix<<<N_TOKENS / 2, 128>>>(beta, y);
}

// round 6
// speedup vs baseline: 1.3410x; 1.1012x over previous
#include <cuda_runtime.h>
#include <cuda_fp16.h>
#include <cstdint>
#include <cstddef>

#define N_TOKENS 8192
#define NGROUP   32

// Scratch (device globals — no runtime allocation).
// g_xm2 : x_mixed fp16 pairs [g][t][i/2]   (64 MB)
// g_yp2 : y_parts fp16 pairs [t][g][o/2]   (64 MB)
// g_wf16: decoded ternary weights fp16 [g][o][k] (1 MB, L2-resident)
__device__ uint32_t g_xm2[(size_t)NGROUP * N_TOKENS * 64];
__device__ uint32_t g_yp2[(size_t)N_TOKENS * NGROUP * 64];
__device__ uint32_t g_wf16[(size_t)NGROUP * 128 * 64];

// ---------------------------------------------------------------------------
__device__ __forceinline__ uint32_t smem_u32(const void* p) {
    uint32_t a;
    asm("{ .reg .u64 t; cvta.to.shared.u64 t, %1; cvt.u32.u64 %0, t; }"
        : "=r"(a) : "l"(p));
    return a;
}

__device__ __forceinline__ void cp16(uint32_t s, const void* g) {
    asm volatile("cp.async.cg.shared.global [%0], [%1], 16;" :: "r"(s), "l"(g));
}
__device__ __forceinline__ void cp_commit_wait() {
    asm volatile("cp.async.commit_group;");
    asm volatile("cp.async.wait_group 0;");
}

__device__ __forceinline__ void ldsm_x4(uint32_t& r0, uint32_t& r1,
                                        uint32_t& r2, uint32_t& r3, uint32_t addr) {
    asm volatile("ldmatrix.sync.aligned.m8n8.x4.shared.b16 {%0,%1,%2,%3}, [%4];"
                 : "=r"(r0), "=r"(r1), "=r"(r2), "=r"(r3) : "r"(addr));
}

__device__ __forceinline__ void mma16816(float* c, const uint32_t* a,
                                         uint32_t b0, uint32_t b1) {
    asm volatile("mma.sync.aligned.m16n8k16.row.col.f32.f16.f16.f32 "
                 "{%0,%1,%2,%3}, {%4,%5,%6,%7}, {%8,%9}, {%0,%1,%2,%3};"
                 : "+f"(c[0]), "+f"(c[1]), "+f"(c[2]), "+f"(c[3])
                 : "r"(a[0]), "r"(a[1]), "r"(a[2]), "r"(a[3]), "r"(b0), "r"(b1));
}

// 8-point unnormalized WHT on float2[8]
__device__ __forceinline__ void wht8(float2* v) {
#pragma unroll
    for (int s = 1; s < 8; s <<= 1) {
#pragma unroll
        for (int e = 0; e < 8; e++) {
            if ((e & s) == 0) {
                float2 a = v[e], b = v[e | s];
                v[e].x = a.x + b.x; v[e].y = a.y + b.y;
                v[e | s].x = a.x - b.x; v[e | s].y = a.y - b.y;
            }
        }
    }
}
// 4-point unnormalized WHT on float2[4]
__device__ __forceinline__ void wht4(float2* v) {
#pragma unroll
    for (int s = 1; s < 4; s <<= 1) {
#pragma unroll
        for (int e = 0; e < 4; e++) {
            if ((e & s) == 0) {
                float2 a = v[e], b = v[e | s];
                v[e].x = a.x + b.x; v[e].y = a.y + b.y;
                v[e | s].x = a.x - b.x; v[e | s].y = a.y - b.y;
            }
        }
    }
}

// ---------------------------------------------------------------------------
// K0: decode packed ternary weights (int32, one byte per element) -> fp16
// matrix g_wf16[g][o][k].
// ---------------------------------------------------------------------------
__global__ void __launch_bounds__(256) k0_decode(const int* __restrict__ wpk) {
    const int g    = blockIdx.x;
    const int o    = threadIdx.x >> 1;
    const int half = threadIdx.x & 1;
    const int* row32 = wpk + ((size_t)g * 128 + o) * 32 + half * 16;
    uint2* dst = (uint2*)(g_wf16 + ((size_t)(g * 128 + o)) * 64 + half * 32);
#pragma unroll
    for (int c = 0; c < 16; c++) {
        uint32_t by = (uint32_t)__ldg(row32 + c) & 0xFFu;
        uint32_t bits[4];
#pragma unroll
        for (int j = 0; j < 4; j++) {
            uint32_t v2 = (by >> (6 - 2 * j)) & 3u;
            bits[j] = (v2 == 1u) ? 0u : ((v2 == 2u) ? 0x3C00u : 0xBC00u);
        }
        dst[c] = make_uint2(bits[0] | (bits[1] << 16), bits[2] | (bits[3] << 16));
    }
}

// ---------------------------------------------------------------------------
// K1: stage-1 Hadamard, radix 8x4 via SMEM. CTA = 2 tokens, 512 threads.
// Phase1: thread (t, g1, ip) : WHT8 over g0. Phase2: thread (t, h0, ip)
// covering 2 h0 each : WHT4 over g1, emit fp16 pairs to g_xm2[h][t][ip].
// ---------------------------------------------------------------------------
__global__ void __launch_bounds__(512) k1_mix(const float* __restrict__ x) {
    __shared__ float2 su[2 * 4 * 8 * 64];           // [t][g1][h0][ip], 32 KB

    const int tid = threadIdx.x;
    const int tl  = tid >> 8;                        // token within CTA
    const int r   = tid & 255;
    const int t   = blockIdx.x * 2 + tl;

    // Phase 1: g1 = r>>6, ip = r&63
    {
        const int g1 = r >> 6, ip = r & 63;
        const float2* xr = (const float2*)(x + (size_t)t * 4096) + g1 * 512 + ip;
        float2 v[8];
#pragma unroll
        for (int g0 = 0; g0 < 8; g0++) v[g0] = __ldcs(xr + g0 * 64);
        wht8(v);
        float2* dst = su + ((tl * 4 + g1) * 8) * 64 + ip;
#pragma unroll
        for (int h0 = 0; h0 < 8; h0++) dst[h0 * 64] = v[h0];
    }
    __syncthreads();

    // Phase 2: h0a = r>>6 covers h0 = {h0a, h0a+4}; ip = r&63
    {
        const int h0a = r >> 6, ip = r & 63;
#pragma unroll
        for (int k = 0; k < 2; k++) {
            const int h0 = h0a + k * 4;
            float2 v[4];
#pragma unroll
            for (int g1 = 0; g1 < 4; g1++)
                v[g1] = su[((tl * 4 + g1) * 8 + h0) * 64 + ip];
            wht4(v);
#pragma unroll
            for (int h1 = 0; h1 < 4; h1++) {
                __half2 h = __floats2half2_rn(v[h1].x, v[h1].y);
                g_xm2[((size_t)(h1 * 8 + h0) * N_TOKENS + t) * 64 + ip] = *(uint32_t*)&h;
            }
        }
    }
}

// ---------------------------------------------------------------------------
// K2: per (token-tile tt, group g, n-half nh):
//   C[128t x 64o] = A[128x128] * B[64x128]^T   fp16 in, fp32 acc.
// 256 threads = 8 warps, warp tile 32(m) x 32(n). 4 CTAs/SM target.
// ---------------------------------------------------------------------------
#define SMS 272                       // smem row stride (bytes)
#define A_BYTES (128 * SMS)           // 34816
#define B_BYTES (64 * SMS)            // 17408
#define K2_SMEM (A_BYTES + B_BYTES)   // 52224

__global__ void __launch_bounds__(256, 4) k2_gemm() {
    extern __shared__ char smem[];
    const uint32_t sA = smem_u32(smem);
    const uint32_t sB = sA + A_BYTES;

    const int tid  = threadIdx.x;
    const int wid  = tid >> 5;
    const int lane = tid & 31;
    const int tt = blockIdx.x;
    const int g  = blockIdx.y;
    const int nh = blockIdx.z;                    // n-half: 0 or 1

    // ---- A fill: 128 rows x 256 B from g_xm2 (cp.async) ----
    {
        const char* src = (const char*)(g_xm2 + ((size_t)g * N_TOKENS + (size_t)tt * 128) * 64);
#pragma unroll
        for (int it = 0; it < 8; it++) {
            int idx = tid + it * 256;
            int rr = idx >> 4, q = idx & 15;
            cp16(sA + rr * SMS + q * 16, src + (size_t)rr * 256 + q * 16);
        }
    }
    // ---- B fill: 64 rows x 256 B from pre-decoded g_wf16 (L2 hit) ----
    {
        const char* srcB = (const char*)(g_wf16 + ((size_t)g * 128 + nh * 64) * 64);
#pragma unroll
        for (int it = 0; it < 4; it++) {
            int idx = tid + it * 256;             // 0..1023
            int rr = idx >> 4, q = idx & 15;
            cp16(sB + rr * SMS + q * 16, srcB + (size_t)rr * 256 + q * 16);
        }
    }
    cp_commit_wait();
    __syncthreads();

    const int wm = (wid & 3) * 32;                // warp m-base
    const int wn = (wid >> 2) * 32;               // warp n-base (within 64)

    const int a_row = (lane & 7) + ((lane >> 3) & 1) * 8;
    const int a_col = ((lane >> 4) & 1) * 16;
    const uint32_t aLane = sA + (wm + a_row) * SMS + a_col;

    const int b_row = (lane & 7) + ((lane >> 4) & 1) * 8;
    const int b_col = ((lane >> 3) & 1) * 16;
    const uint32_t bLane = sB + (wn + b_row) * SMS + b_col;

    float acc[2][4][4];
#pragma unroll
    for (int mt = 0; mt < 2; mt++)
#pragma unroll
        for (int nt = 0; nt < 4; nt++)
#pragma unroll
            for (int q = 0; q < 4; q++) acc[mt][nt][q] = 0.0f;

#pragma unroll
    for (int ks = 0; ks < 8; ks++) {
        uint32_t a[2][4];
#pragma unroll
        for (int mt = 0; mt < 2; mt++)
            ldsm_x4(a[mt][0], a[mt][1], a[mt][2], a[mt][3],
                    aLane + mt * 16 * SMS + ks * 32);
        uint32_t b[2][4];
#pragma unroll
        for (int n2 = 0; n2 < 2; n2++)
            ldsm_x4(b[n2][0], b[n2][1], b[n2][2], b[n2][3],
                    bLane + n2 * 16 * SMS + ks * 32);
#pragma unroll
        for (int mt = 0; mt < 2; mt++)
#pragma unroll
            for (int nt = 0; nt < 4; nt++) {
                uint32_t b0 = b[nt >> 1][(nt & 1) * 2 + 0];
                uint32_t b1 = b[nt >> 1][(nt & 1) * 2 + 1];
                mma16816(acc[mt][nt], a[mt], b0, b1);
            }
    }

    // ---- epilogue: fp16x2 stores to g_yp2 [t][g][o/2] ----
    const int m0 = tt * 128 + wm + (lane >> 2);
    const int n0 = wn + 2 * (lane & 3);
#pragma unroll
    for (int mt = 0; mt < 2; mt++) {
#pragma unroll
        for (int nt = 0; nt < 4; nt++) {
            int n = nh * 64 + n0 + nt * 8;        // global o column (even)
            __half2 lo = __floats2half2_rn(acc[mt][nt][0], acc[mt][nt][1]);
            __half2 hi = __floats2half2_rn(acc[mt][nt][2], acc[mt][nt][3]);
            size_t r0 = ((size_t)(m0 + mt * 16) * 32 + g) * 64 + (n >> 1);
            size_t r1 = ((size_t)(m0 + mt * 16 + 8) * 32 + g) * 64 + (n >> 1);
            g_yp2[r0] = *(uint32_t*)&lo;
            g_yp2[r1] = *(uint32_t*)&hi;
        }
    }
}

// ---------------------------------------------------------------------------
// K3: stage-3 Hadamard + beta/32, radix 8x4 via SMEM. CTA = 2 tokens,
// 512 threads. Same structure as K1; input fp16 pairs, output fp32.
// ---------------------------------------------------------------------------
__global__ void __launch_bounds__(512) k3_mix(const float* __restrict__ beta,
                                              float* __restrict__ y) {
    __shared__ float2 su[2 * 4 * 8 * 64];           // [t][g1][h0][op], 32 KB

    const int tid = threadIdx.x;
    const int tl  = tid >> 8;
    const int r   = tid & 255;
    const int t   = blockIdx.x * 2 + tl;

    // Phase 1: g1 = r>>6, op = r&63 : WHT8 over g0
    {
        const int g1 = r >> 6, op = r & 63;
        const uint32_t* yr = g_yp2 + (size_t)t * 2048 + g1 * 512 + op;
        float2 v[8];
#pragma unroll
        for (int g0 = 0; g0 < 8; g0++) {
            uint32_t pk = __ldcs(yr + g0 * 64);
            v[g0] = __half22float2(*(__half2*)&pk);
        }
        wht8(v);
        float2* dst = su + ((tl * 4 + g1) * 8) * 64 + op;
#pragma unroll
        for (int h0 = 0; h0 < 8; h0++) dst[h0 * 64] = v[h0];
    }
    __syncthreads();

    // Phase 2: h0a = r>>6 covers h0 = {h0a, h0a+4}; op = r&63
    {
        const int h0a = r >> 6, op = r & 63;
        const float s0 = __ldg(beta + 2 * op)     * (1.0f / 32.0f);
        const float s1 = __ldg(beta + 2 * op + 1) * (1.0f / 32.0f);
        float2* out = (float2*)(y + (size_t)t * 4096) + op;
#pragma unroll
        for (int k = 0; k < 2; k++) {
            const int h0 = h0a + k * 4;
            float2 v[4];
#pragma unroll
            for (int g1 = 0; g1 < 4; g1++)
                v[g1] = su[((tl * 4 + g1) * 8 + h0) * 64 + op];
            wht4(v);
#pragma unroll
            for (int h1 = 0; h1 < 4; h1++) {
                float2 o;
                o.x = v[h1].x * s0;
                o.y = v[h1].y * s1;
                __stcs(out + (h1 * 8 + h0) * 64, o);
            }
        }
    }
}

// ---------------------------------------------------------------------------
// Launch: inputs dispatched BY ELEMENT COUNT (order-proof).
// ---------------------------------------------------------------------------
extern "C" void kernel_launch(void* const* d_in, const int* in_sizes, int n_in,
                              void* d_out, int out_size) {
    const float* x    = nullptr;
    const int*   wp   = nullptr;
    const float* beta = nullptr;

    for (int i = 0; i < n_in; i++) {
        switch (in_sizes[i]) {
            case 33554432: x    = (const float*)d_in[i]; break;
            case 131072:   wp   = (const int*)d_in[i];   break;
            case 128:      beta = (const float*)d_in[i]; break;
            default: break;   // H (1024) ignored
        }
    }
    if (!x)    x    = (const float*)d_in[0];
    if (!wp)   wp   = (const int*)d_in[1];
    if (!beta) beta = (const float*)d_in[2];

    float* y = (float*)d_out;

    cudaFuncSetAttribute(k2_gemm, cudaFuncAttributeMaxDynamicSharedMemorySize, K2_SMEM);

    k0_decode<<<NGROUP, 256>>>(wp);
    k1_mix<<<N_TOKENS / 2, 512>>>(x);
    k2_gemm<<<dim3(N_TOKENS / 128, NGROUP, 2), 256, K2_SMEM>>>();
    k3_mix<<<N_TOKENS / 2, 512>>>(beta, y);
}

// round 7
// speedup vs baseline: 1.4665x; 1.0936x over previous
#include <cuda_runtime.h>
#include <cuda_fp16.h>
#include <cstdint>
#include <cstddef>

#define N_TOKENS 8192
#define NGROUP   32

// Scratch (device globals — no runtime allocation).
// g_xm2 : x_mixed fp16 pairs [g][t][i/2]   (64 MB)
// g_yp2 : y_parts fp16 pairs [t][g][o/2]   (64 MB)
// g_wf16: decoded ternary weights fp16 [g][o][k] (1 MB, L2-resident)
__device__ uint32_t g_xm2[(size_t)NGROUP * N_TOKENS * 64];
__device__ uint32_t g_yp2[(size_t)N_TOKENS * NGROUP * 64];
__device__ uint32_t g_wf16[(size_t)NGROUP * 128 * 64];

// ---------------------------------------------------------------------------
__device__ __forceinline__ uint32_t smem_u32(const void* p) {
    uint32_t a;
    asm("{ .reg .u64 t; cvta.to.shared.u64 t, %1; cvt.u32.u64 %0, t; }"
        : "=r"(a) : "l"(p));
    return a;
}

__device__ __forceinline__ void cp16(uint32_t s, const void* g) {
    asm volatile("cp.async.cg.shared.global [%0], [%1], 16;" :: "r"(s), "l"(g));
}
__device__ __forceinline__ void cp_commit_wait() {
    asm volatile("cp.async.commit_group;");
    asm volatile("cp.async.wait_group 0;");
}

__device__ __forceinline__ void ldsm_x4(uint32_t& r0, uint32_t& r1,
                                        uint32_t& r2, uint32_t& r3, uint32_t addr) {
    asm volatile("ldmatrix.sync.aligned.m8n8.x4.shared.b16 {%0,%1,%2,%3}, [%4];"
                 : "=r"(r0), "=r"(r1), "=r"(r2), "=r"(r3) : "r"(addr));
}

__device__ __forceinline__ void mma16816(float* c, const uint32_t* a,
                                         uint32_t b0, uint32_t b1) {
    asm volatile("mma.sync.aligned.m16n8k16.row.col.f32.f16.f16.f32 "
                 "{%0,%1,%2,%3}, {%4,%5,%6,%7}, {%8,%9}, {%0,%1,%2,%3};"
                 : "+f"(c[0]), "+f"(c[1]), "+f"(c[2]), "+f"(c[3])
                 : "r"(a[0]), "r"(a[1]), "r"(a[2]), "r"(a[3]), "r"(b0), "r"(b1));
}

// Unnormalized WHT butterflies on float4 lanes
__device__ __forceinline__ void bfly4(float4& a, float4& b) {
    float4 ta = a, tb = b;
    a.x = ta.x + tb.x; a.y = ta.y + tb.y; a.z = ta.z + tb.z; a.w = ta.w + tb.w;
    b.x = ta.x - tb.x; b.y = ta.y - tb.y; b.z = ta.z - tb.z; b.w = ta.w - tb.w;
}
__device__ __forceinline__ void wht8(float4* v) {
#pragma unroll
    for (int s = 1; s < 8; s <<= 1)
#pragma unroll
        for (int e = 0; e < 8; e++)
            if ((e & s) == 0) bfly4(v[e], v[e | s]);
}
__device__ __forceinline__ void wht4(float4* v) {
#pragma unroll
    for (int s = 1; s < 4; s <<= 1)
#pragma unroll
        for (int e = 0; e < 4; e++)
            if ((e & s) == 0) bfly4(v[e], v[e | s]);
}

// ---------------------------------------------------------------------------
// K0: decode packed ternary weights (int32, one byte per element) -> fp16
// matrix g_wf16[g][o][k].
// ---------------------------------------------------------------------------
__global__ void __launch_bounds__(256) k0_decode(const int* __restrict__ wpk) {
    const int g    = blockIdx.x;
    const int o    = threadIdx.x >> 1;
    const int half = threadIdx.x & 1;
    const int* row32 = wpk + ((size_t)g * 128 + o) * 32 + half * 16;
    uint2* dst = (uint2*)(g_wf16 + ((size_t)(g * 128 + o)) * 64 + half * 32);
#pragma unroll
    for (int c = 0; c < 16; c++) {
        uint32_t by = (uint32_t)__ldg(row32 + c) & 0xFFu;
        uint32_t bits[4];
#pragma unroll
        for (int j = 0; j < 4; j++) {
            uint32_t v2 = (by >> (6 - 2 * j)) & 3u;
            bits[j] = (v2 == 1u) ? 0u : ((v2 == 2u) ? 0x3C00u : 0xBC00u);
        }
        dst[c] = make_uint2(bits[0] | (bits[1] << 16), bits[2] | (bits[3] << 16));
    }
}

// ---------------------------------------------------------------------------
// K1: stage-1 Hadamard, radix 8x4 via SMEM, float4 lanes.
// CTA = 2 tokens, 256 threads: (tl, g1, iq) with iq indexing float4 (4 floats).
// ---------------------------------------------------------------------------
__global__ void __launch_bounds__(256) k1_mix(const float* __restrict__ x) {
    __shared__ float4 su[2 * 4 * 8 * 32];           // [tl][g1][h0][iq], 32 KB

    const int tid = threadIdx.x;
    const int tl  = tid >> 7;
    const int r   = tid & 127;
    const int t   = blockIdx.x * 2 + tl;
    const int iq  = r & 31;

    // Phase 1: WHT8 over g0 (g = g1*8+g0)
    {
        const int g1 = r >> 5;
        const float4* xr = (const float4*)(x + (size_t)t * 4096) + g1 * 256 + iq;
        float4 v[8];
#pragma unroll
        for (int g0 = 0; g0 < 8; g0++) v[g0] = __ldcs(xr + g0 * 32);
        wht8(v);
        float4* dst = su + ((tl * 4 + g1) * 8) * 32 + iq;
#pragma unroll
        for (int h0 = 0; h0 < 8; h0++) dst[h0 * 32] = v[h0];
    }
    __syncthreads();

    // Phase 2: WHT4 over g1, two h0 per thread
    {
        const int h0a = r >> 5;
        uint2* xm = (uint2*)g_xm2;
#pragma unroll
        for (int k = 0; k < 2; k++) {
            const int h0 = h0a + k * 4;
            float4 v[4];
#pragma unroll
            for (int g1 = 0; g1 < 4; g1++)
                v[g1] = su[((tl * 4 + g1) * 8 + h0) * 32 + iq];
            wht4(v);
#pragma unroll
            for (int h1 = 0; h1 < 4; h1++) {
                __half2 lo = __floats2half2_rn(v[h1].x, v[h1].y);
                __half2 hi = __floats2half2_rn(v[h1].z, v[h1].w);
                xm[((size_t)(h1 * 8 + h0) * N_TOKENS + t) * 32 + iq] =
                    make_uint2(*(uint32_t*)&lo, *(uint32_t*)&hi);
            }
        }
    }
}

// ---------------------------------------------------------------------------
// K2: per (nh, tt, g): C[128t x 64o] = A[128x128] * B[64x128]^T, fp16->fp32.
// Grid ordered (nh, tt, g) so the two CTAs sharing an A tile are adjacent
// in launch order -> second A read is an L2 hit.
// ---------------------------------------------------------------------------
#define SMS 272                       // smem row stride (bytes)
#define A_BYTES (128 * SMS)           // 34816
#define B_BYTES (64 * SMS)            // 17408
#define K2_SMEM (A_BYTES + B_BYTES)   // 52224

__global__ void __launch_bounds__(256, 4) k2_gemm() {
    extern __shared__ char smem[];
    const uint32_t sA = smem_u32(smem);
    const uint32_t sB = sA + A_BYTES;

    const int tid  = threadIdx.x;
    const int wid  = tid >> 5;
    const int lane = tid & 31;
    const int nh = blockIdx.x;                    // n-half: 0 or 1
    const int tt = blockIdx.y;
    const int g  = blockIdx.z;

    // ---- A fill: 128 rows x 256 B from g_xm2 (cp.async) ----
    {
        const char* src = (const char*)(g_xm2 + ((size_t)g * N_TOKENS + (size_t)tt * 128) * 64);
#pragma unroll
        for (int it = 0; it < 8; it++) {
            int idx = tid + it * 256;
            int rr = idx >> 4, q = idx & 15;
            cp16(sA + rr * SMS + q * 16, src + (size_t)rr * 256 + q * 16);
        }
    }
    // ---- B fill: 64 rows x 256 B from pre-decoded g_wf16 (L2 hit) ----
    {
        const char* srcB = (const char*)(g_wf16 + ((size_t)g * 128 + nh * 64) * 64);
#pragma unroll
        for (int it = 0; it < 4; it++) {
            int idx = tid + it * 256;
            int rr = idx >> 4, q = idx & 15;
            cp16(sB + rr * SMS + q * 16, srcB + (size_t)rr * 256 + q * 16);
        }
    }
    cp_commit_wait();
    __syncthreads();

    const int wm = (wid & 3) * 32;
    const int wn = (wid >> 2) * 32;

    const int a_row = (lane & 7) + ((lane >> 3) & 1) * 8;
    const int a_col = ((lane >> 4) & 1) * 16;
    const uint32_t aLane = sA + (wm + a_row) * SMS + a_col;

    const int b_row = (lane & 7) + ((lane >> 4) & 1) * 8;
    const int b_col = ((lane >> 3) & 1) * 16;
    const uint32_t bLane = sB + (wn + b_row) * SMS + b_col;

    float acc[2][4][4];
#pragma unroll
    for (int mt = 0; mt < 2; mt++)
#pragma unroll
        for (int nt = 0; nt < 4; nt++)
#pragma unroll
            for (int q = 0; q < 4; q++) acc[mt][nt][q] = 0.0f;

#pragma unroll
    for (int ks = 0; ks < 8; ks++) {
        uint32_t a[2][4];
#pragma unroll
        for (int mt = 0; mt < 2; mt++)
            ldsm_x4(a[mt][0], a[mt][1], a[mt][2], a[mt][3],
                    aLane + mt * 16 * SMS + ks * 32);
        uint32_t b[2][4];
#pragma unroll
        for (int n2 = 0; n2 < 2; n2++)
            ldsm_x4(b[n2][0], b[n2][1], b[n2][2], b[n2][3],
                    bLane + n2 * 16 * SMS + ks * 32);
#pragma unroll
        for (int mt = 0; mt < 2; mt++)
#pragma unroll
            for (int nt = 0; nt < 4; nt++) {
                uint32_t b0 = b[nt >> 1][(nt & 1) * 2 + 0];
                uint32_t b1 = b[nt >> 1][(nt & 1) * 2 + 1];
                mma16816(acc[mt][nt], a[mt], b0, b1);
            }
    }

    // ---- epilogue: fp16x2 stores to g_yp2 [t][g][o/2] ----
    const int m0 = tt * 128 + wm + (lane >> 2);
    const int n0 = wn + 2 * (lane & 3);
#pragma unroll
    for (int mt = 0; mt < 2; mt++) {
#pragma unroll
        for (int nt = 0; nt < 4; nt++) {
            int n = nh * 64 + n0 + nt * 8;
            __half2 lo = __floats2half2_rn(acc[mt][nt][0], acc[mt][nt][1]);
            __half2 hi = __floats2half2_rn(acc[mt][nt][2], acc[mt][nt][3]);
            size_t r0 = ((size_t)(m0 + mt * 16) * 32 + g) * 64 + (n >> 1);
            size_t r1 = ((size_t)(m0 + mt * 16 + 8) * 32 + g) * 64 + (n >> 1);
            g_yp2[r0] = *(uint32_t*)&lo;
            g_yp2[r1] = *(uint32_t*)&hi;
        }
    }
}

// ---------------------------------------------------------------------------
// K3: stage-3 Hadamard + beta/32, radix 8x4 via SMEM, float4 lanes.
// CTA = 2 tokens, 256 threads.
// ---------------------------------------------------------------------------
__global__ void __launch_bounds__(256) k3_mix(const float* __restrict__ beta,
                                              float* __restrict__ y) {
    __shared__ float4 su[2 * 4 * 8 * 32];           // 32 KB

    const int tid = threadIdx.x;
    const int tl  = tid >> 7;
    const int r   = tid & 127;
    const int t   = blockIdx.x * 2 + tl;
    const int oq  = r & 31;

    // Phase 1: WHT8 over g0
    {
        const int g1 = r >> 5;
        const uint2* yr = (const uint2*)g_yp2 + (size_t)t * 1024 + g1 * 256 + oq;
        float4 v[8];
#pragma unroll
        for (int g0 = 0; g0 < 8; g0++) {
            uint2 pk = __ldcs(yr + g0 * 32);
            float2 a = __half22float2(*(__half2*)&pk.x);
            float2 b = __half22float2(*(__half2*)&pk.y);
            v[g0] = make_float4(a.x, a.y, b.x, b.y);
        }
        wht8(v);
        float4* dst = su + ((tl * 4 + g1) * 8) * 32 + oq;
#pragma unroll
        for (int h0 = 0; h0 < 8; h0++) dst[h0 * 32] = v[h0];
    }
    __syncthreads();

    // Phase 2: WHT4 over g1, scale by beta/32, write fp32 y
    {
        const int h0a = r >> 5;
        const float4 bb = __ldg((const float4*)beta + oq);
        const float s0 = bb.x * (1.0f / 32.0f), s1 = bb.y * (1.0f / 32.0f);
        const float s2 = bb.z * (1.0f / 32.0f), s3 = bb.w * (1.0f / 32.0f);
        float4* out = (float4*)(y + (size_t)t * 4096) + oq;
#pragma unroll
        for (int k = 0; k < 2; k++) {
            const int h0 = h0a + k * 4;
            float4 v[4];
#pragma unroll
            for (int g1 = 0; g1 < 4; g1++)
                v[g1] = su[((tl * 4 + g1) * 8 + h0) * 32 + oq];
            wht4(v);
#pragma unroll
            for (int h1 = 0; h1 < 4; h1++) {
                float4 o;
                o.x = v[h1].x * s0; o.y = v[h1].y * s1;
                o.z = v[h1].z * s2; o.w = v[h1].w * s3;
                __stcs(out + (h1 * 8 + h0) * 32, o);
            }
        }
    }
}

// ---------------------------------------------------------------------------
// Launch: inputs dispatched BY ELEMENT COUNT (order-proof).
// ---------------------------------------------------------------------------
extern "C" void kernel_launch(void* const* d_in, const int* in_sizes, int n_in,
                              void* d_out, int out_size) {
    const float* x    = nullptr;
    const int*   wp   = nullptr;
    const float* beta = nullptr;

    for (int i = 0; i < n_in; i++) {
        switch (in_sizes[i]) {
            case 33554432: x    = (const float*)d_in[i]; break;
            case 131072:   wp   = (const int*)d_in[i];   break;
            case 128:      beta = (const float*)d_in[i]; break;
            default: break;   // H (1024) ignored
        }
    }
    if (!x)    x    = (const float*)d_in[0];
    if (!wp)   wp   = (const int*)d_in[1];
    if (!beta) beta = (const float*)d_in[2];

    float* y = (float*)d_out;

    cudaFuncSetAttribute(k2_gemm, cudaFuncAttributeMaxDynamicSharedMemorySize, K2_SMEM);

    k0_decode<<<NGROUP, 256>>>(wp);
    k1_mix<<<N_TOKENS / 2, 256>>>(x);
    k2_gemm<<<dim3(2, N_TOKENS / 128, NGROUP), 256, K2_SMEM>>>();
    k3_mix<<<N_TOKENS / 2, 256>>>(beta, y);
}

// round 9
// speedup vs baseline: 1.5541x; 1.0597x over previous
#include <cuda_runtime.h>
#include <cuda_fp16.h>
#include <cstdint>
#include <cstddef>

#define N_TOKENS 8192
#define NGROUP   32

// Scratch (device globals — no runtime allocation).
__device__ uint32_t g_xm2[(size_t)NGROUP * N_TOKENS * 64];   // x_mixed fp16 [g][t][i/2]
__device__ uint32_t g_yp2[(size_t)N_TOKENS * NGROUP * 64];   // y_parts fp16 [t][g][o/2]
__device__ uint32_t g_wf16[(size_t)NGROUP * 128 * 64];       // decoded W fp16 [g][o][k]

// ---------------------------------------------------------------------------
__device__ __forceinline__ uint32_t smem_u32(const void* p) {
    uint32_t a;
    asm("{ .reg .u64 t; cvta.to.shared.u64 t, %1; cvt.u32.u64 %0, t; }"
        : "=r"(a) : "l"(p));
    return a;
}

__device__ __forceinline__ void cp16(uint32_t s, const void* g) {
    asm volatile("cp.async.cg.shared.global [%0], [%1], 16;" :: "r"(s), "l"(g));
}
__device__ __forceinline__ void cp_commit_wait() {
    asm volatile("cp.async.commit_group;");
    asm volatile("cp.async.wait_group 0;");
}

__device__ __forceinline__ void ldsm_x4(uint32_t& r0, uint32_t& r1,
                                        uint32_t& r2, uint32_t& r3, uint32_t addr) {
    asm volatile("ldmatrix.sync.aligned.m8n8.x4.shared.b16 {%0,%1,%2,%3}, [%4];"
                 : "=r"(r0), "=r"(r1), "=r"(r2), "=r"(r3) : "r"(addr));
}

__device__ __forceinline__ void mma16816(float* c, const uint32_t* a,
                                         uint32_t b0, uint32_t b1) {
    asm volatile("mma.sync.aligned.m16n8k16.row.col.f32.f16.f16.f32 "
                 "{%0,%1,%2,%3}, {%4,%5,%6,%7}, {%8,%9}, {%0,%1,%2,%3};"
                 : "+f"(c[0]), "+f"(c[1]), "+f"(c[2]), "+f"(c[3])
                 : "r"(a[0]), "r"(a[1]), "r"(a[2]), "r"(a[3]), "r"(b0), "r"(b1));
}

// Unnormalized WHT butterflies on float4 lanes
__device__ __forceinline__ void bfly4(float4& a, float4& b) {
    float4 ta = a, tb = b;
    a.x = ta.x + tb.x; a.y = ta.y + tb.y; a.z = ta.z + tb.z; a.w = ta.w + tb.w;
    b.x = ta.x - tb.x; b.y = ta.y - tb.y; b.z = ta.z - tb.z; b.w = ta.w - tb.w;
}
__device__ __forceinline__ void wht8(float4* v) {
#pragma unroll
    for (int s = 1; s < 8; s <<= 1)
#pragma unroll
        for (int e = 0; e < 8; e++)
            if ((e & s) == 0) bfly4(v[e], v[e | s]);
}
__device__ __forceinline__ void wht4(float4* v) {
#pragma unroll
    for (int s = 1; s < 4; s <<= 1)
#pragma unroll
        for (int e = 0; e < 4; e++)
            if ((e & s) == 0) bfly4(v[e], v[e | s]);
}

// ---------------------------------------------------------------------------
// K0: decode packed ternary weights (int32, one byte each) -> fp16 g_wf16.
// ---------------------------------------------------------------------------
__global__ void __launch_bounds__(256) k0_decode(const int* __restrict__ wpk) {
    const int g    = blockIdx.x;
    const int o    = threadIdx.x >> 1;
    const int half = threadIdx.x & 1;
    const int* row32 = wpk + ((size_t)g * 128 + o) * 32 + half * 16;
    uint2* dst = (uint2*)(g_wf16 + ((size_t)(g * 128 + o)) * 64 + half * 32);
#pragma unroll
    for (int c = 0; c < 16; c++) {
        uint32_t by = (uint32_t)__ldg(row32 + c) & 0xFFu;
        uint32_t bits[4];
#pragma unroll
        for (int j = 0; j < 4; j++) {
            uint32_t v2 = (by >> (6 - 2 * j)) & 3u;
            bits[j] = (v2 == 1u) ? 0u : ((v2 == 2u) ? 0x3C00u : 0xBC00u);
        }
        dst[c] = make_uint2(bits[0] | (bits[1] << 16), bits[2] | (bits[3] << 16));
    }
}

// ---------------------------------------------------------------------------
// K1: stage-1 Hadamard (radix 8x4 via SMEM, float4 lanes). CTA = 2 tokens.
// ---------------------------------------------------------------------------
__global__ void __launch_bounds__(256) k1_mix(const float* __restrict__ x) {
    __shared__ float4 su[2 * 4 * 8 * 32];           // 32 KB

    const int tid = threadIdx.x;
    const int tl  = tid >> 7;
    const int r   = tid & 127;
    const int t   = blockIdx.x * 2 + tl;
    const int iq  = r & 31;

    {
        const int g1 = r >> 5;
        const float4* xr = (const float4*)(x + (size_t)t * 4096) + g1 * 256 + iq;
        float4 v[8];
#pragma unroll
        for (int g0 = 0; g0 < 8; g0++) v[g0] = __ldcs(xr + g0 * 32);
        wht8(v);
        float4* dst = su + ((tl * 4 + g1) * 8) * 32 + iq;
#pragma unroll
        for (int h0 = 0; h0 < 8; h0++) dst[h0 * 32] = v[h0];
    }
    __syncthreads();
    {
        const int h0a = r >> 5;
        uint2* xm = (uint2*)g_xm2;
#pragma unroll
        for (int k = 0; k < 2; k++) {
            const int h0 = h0a + k * 4;
            float4 v[4];
#pragma unroll
            for (int g1 = 0; g1 < 4; g1++)
                v[g1] = su[((tl * 4 + g1) * 8 + h0) * 32 + iq];
            wht4(v);
#pragma unroll
            for (int h1 = 0; h1 < 4; h1++) {
                __half2 lo = __floats2half2_rn(v[h1].x, v[h1].y);
                __half2 hi = __floats2half2_rn(v[h1].z, v[h1].w);
                xm[((size_t)(h1 * 8 + h0) * N_TOKENS + t) * 32 + iq] =
                    make_uint2(*(uint32_t*)&lo, *(uint32_t*)&hi);
            }
        }
    }
}

// ---------------------------------------------------------------------------
// K2: per (nh, tt, g): C[128t x 64o] = A[128x128] * B[64x128]^T, fp16->fp32.
// Grid ordered (nh, tt, g): CTAs sharing an A tile are adjacent (L2 reuse).
// Epilogue stages C through SMEM (reusing the A region) so global stores are
// fully coalesced 128B rows instead of scattered 16B fragments.
// ---------------------------------------------------------------------------
#define SMS 272
#define A_BYTES (128 * SMS)
#define B_BYTES (64 * SMS)
#define K2_SMEM (A_BYTES + B_BYTES)
#define CSTRIDE 36                     // C-stage row stride in u32 (144 B, pad)

__global__ void __launch_bounds__(256, 4) k2_gemm() {
    extern __shared__ char smem[];
    const uint32_t sA = smem_u32(smem);
    const uint32_t sB = sA + A_BYTES;

    const int tid  = threadIdx.x;
    const int wid  = tid >> 5;
    const int lane = tid & 31;
    const int nh = blockIdx.x;
    const int tt = blockIdx.y;
    const int g  = blockIdx.z;

    {
        const char* src = (const char*)(g_xm2 + ((size_t)g * N_TOKENS + (size_t)tt * 128) * 64);
#pragma unroll
        for (int it = 0; it < 8; it++) {
            int idx = tid + it * 256;
            int rr = idx >> 4, q = idx & 15;
            cp16(sA + rr * SMS + q * 16, src + (size_t)rr * 256 + q * 16);
        }
    }
    {
        const char* srcB = (const char*)(g_wf16 + ((size_t)g * 128 + nh * 64) * 64);
#pragma unroll
        for (int it = 0; it < 4; it++) {
            int idx = tid + it * 256;
            int rr = idx >> 4, q = idx & 15;
            cp16(sB + rr * SMS + q * 16, srcB + (size_t)rr * 256 + q * 16);
        }
    }
    cp_commit_wait();
    __syncthreads();

    const int wm = (wid & 3) * 32;
    const int wn = (wid >> 2) * 32;

    const int a_row = (lane & 7) + ((lane >> 3) & 1) * 8;
    const int a_col = ((lane >> 4) & 1) * 16;
    const uint32_t aLane = sA + (wm + a_row) * SMS + a_col;

    const int b_row = (lane & 7) + ((lane >> 4) & 1) * 8;
    const int b_col = ((lane >> 3) & 1) * 16;
    const uint32_t bLane = sB + (wn + b_row) * SMS + b_col;

    float acc[2][4][4];
#pragma unroll
    for (int mt = 0; mt < 2; mt++)
#pragma unroll
        for (int nt = 0; nt < 4; nt++)
#pragma unroll
            for (int q = 0; q < 4; q++) acc[mt][nt][q] = 0.0f;

#pragma unroll
    for (int ks = 0; ks < 8; ks++) {
        uint32_t a[2][4];
#pragma unroll
        for (int mt = 0; mt < 2; mt++)
            ldsm_x4(a[mt][0], a[mt][1], a[mt][2], a[mt][3],
                    aLane + mt * 16 * SMS + ks * 32);
        uint32_t b[2][4];
#pragma unroll
        for (int n2 = 0; n2 < 2; n2++)
            ldsm_x4(b[n2][0], b[n2][1], b[n2][2], b[n2][3],
                    bLane + n2 * 16 * SMS + ks * 32);
#pragma unroll
        for (int mt = 0; mt < 2; mt++)
#pragma unroll
            for (int nt = 0; nt < 4; nt++) {
                uint32_t b0 = b[nt >> 1][(nt & 1) * 2 + 0];
                uint32_t b1 = b[nt >> 1][(nt & 1) * 2 + 1];
                mma16816(acc[mt][nt], a[mt], b0, b1);
            }
    }

    // ---- epilogue: stage fp16x2 C tile in SMEM (reuse A region), then
    //      write coalesced 128B rows to g_yp2 [t][g][o/2] ----
    __syncthreads();                               // all ldsm reads of sA done
    {
        const int rbase = wm + (lane >> 2);        // token row within tile
        const int cu    = (wn >> 1) + 2 * 0 + (lane & 3);  // u32 col base (see below)
#pragma unroll
        for (int mt = 0; mt < 2; mt++) {
#pragma unroll
            for (int nt = 0; nt < 4; nt++) {
                int colu = (wn >> 1) + nt * 4 + (lane & 3);   // 0..31 (u32 within 64-o half)
                __half2 lo = __floats2half2_rn(acc[mt][nt][0], acc[mt][nt][1]);
                __half2 hi = __floats2half2_rn(acc[mt][nt][2], acc[mt][nt][3]);
                int r0 = rbase + mt * 16;
                *(uint32_t*)(smem + (size_t)r0 * (CSTRIDE * 4) + (size_t)colu * 4) = *(uint32_t*)&lo;
                *(uint32_t*)(smem + (size_t)(r0 + 8) * (CSTRIDE * 4) + (size_t)colu * 4) = *(uint32_t*)&hi;
            }
        }
        (void)cu;
    }
    __syncthreads();
    {
        // 128 rows x 32 u32 -> 1024 uint4 copies, coalesced 128B per row
        uint32_t* ypbase = g_yp2 + ((size_t)tt * 128 * 32 + g) * 64 + nh * 32;
#pragma unroll
        for (int it = 0; it < 4; it++) {
            int idx = tid + it * 256;              // 0..1023
            int row = idx >> 3, q = idx & 7;
            uint4 v = *(const uint4*)(smem + (size_t)row * (CSTRIDE * 4) + (size_t)q * 16);
            *(uint4*)(ypbase + (size_t)row * 32 * 64 + q * 4) = v;
        }
    }
}

// ---------------------------------------------------------------------------
// K3: stage-3 Hadamard + beta/32 (radix 8x4 via SMEM). CTA = 2 tokens.
// ---------------------------------------------------------------------------
__global__ void __launch_bounds__(256) k3_mix(const float* __restrict__ beta,
                                              float* __restrict__ y) {
    __shared__ float4 su[2 * 4 * 8 * 32];

    const int tid = threadIdx.x;
    const int tl  = tid >> 7;
    const int r   = tid & 127;
    const int t   = blockIdx.x * 2 + tl;
    const int oq  = r & 31;

    {
        const int g1 = r >> 5;
        const uint2* yr = (const uint2*)g_yp2 + (size_t)t * 1024 + g1 * 256 + oq;
        float4 v[8];
#pragma unroll
        for (int g0 = 0; g0 < 8; g0++) {
            uint2 pk = __ldcs(yr + g0 * 32);
            float2 a = __half22float2(*(__half2*)&pk.x);
            float2 b = __half22float2(*(__half2*)&pk.y);
            v[g0] = make_float4(a.x, a.y, b.x, b.y);
        }
        wht8(v);
        float4* dst = su + ((tl * 4 + g1) * 8) * 32 + oq;
#pragma unroll
        for (int h0 = 0; h0 < 8; h0++) dst[h0 * 32] = v[h0];
    }
    __syncthreads();
    {
        const int h0a = r >> 5;
        const float4 bb = __ldg((const float4*)beta + oq);
        const float s0 = bb.x * (1.0f / 32.0f), s1 = bb.y * (1.0f / 32.0f);
        const float s2 = bb.z * (1.0f / 32.0f), s3 = bb.w * (1.0f / 32.0f);
        float4* out = (float4*)(y + (size_t)t * 4096) + oq;
#pragma unroll
        for (int k = 0; k < 2; k++) {
            const int h0 = h0a + k * 4;
            float4 v[4];
#pragma unroll
            for (int g1 = 0; g1 < 4; g1++)
                v[g1] = su[((tl * 4 + g1) * 8 + h0) * 32 + oq];
            wht4(v);
#pragma unroll
            for (int h1 = 0; h1 < 4; h1++) {
                float4 o;
                o.x = v[h1].x * s0; o.y = v[h1].y * s1;
                o.z = v[h1].z * s2; o.w = v[h1].w * s3;
                __stcs(out + (h1 * 8 + h0) * 32, o);
            }
        }
    }
}

// ---------------------------------------------------------------------------
// Launch: single stream (multi-stream fork/join allocates device memory and
// violates the harness rules). Inputs dispatched BY ELEMENT COUNT.
// ---------------------------------------------------------------------------
extern "C" void kernel_launch(void* const* d_in, const int* in_sizes, int n_in,
                              void* d_out, int out_size) {
    const float* x    = nullptr;
    const int*   wp   = nullptr;
    const float* beta = nullptr;

    for (int i = 0; i < n_in; i++) {
        switch (in_sizes[i]) {
            case 33554432: x    = (const float*)d_in[i]; break;
            case 131072:   wp   = (const int*)d_in[i];   break;
            case 128:      beta = (const float*)d_in[i]; break;
            default: break;   // H (1024) ignored
        }
    }
    if (!x)    x    = (const float*)d_in[0];
    if (!wp)   wp   = (const int*)d_in[1];
    if (!beta) beta = (const float*)d_in[2];

    float* y = (float*)d_out;

    cudaFuncSetAttribute(k2_gemm, cudaFuncAttributeMaxDynamicSharedMemorySize, K2_SMEM);

    k0_decode<<<NGROUP, 256>>>(wp);
    k1_mix<<<N_TOKENS / 2, 256>>>(x);
    k2_gemm<<<dim3(2, N_TOKENS / 128, NGROUP), 256, K2_SMEM>>>();
    k3_mix<<<N_TOKENS / 2, 256>>>(beta, y);
}